// round 5
// baseline (speedup 1.0000x reference)
#include <cuda_runtime.h>
#include <cstdint>

// Problem constants
#define T_DIM 8
#define C_DIM 4
#define NMAPS (T_DIM * C_DIM)        // 32
#define H_DIM 1024
#define W_DIM 1024
#define NUM_GRID 16
#define NCELLS (NUM_GRID * NUM_GRID) // 256
#define THRESH 0.65f
#define NUM_FG 40
#define NUM_BG 1
#define MAX_PTS 42

#define BLOCKS_PER_MAP 16            // one block per grid-row (16 cells)
#define NSTAGES 3                    // cp.async pipeline depth
#define RPS 4                        // image rows per stage
#define NSTAGES_TOT 16               // 64 rows / RPS

// Scratch (__device__ globals; no allocations allowed)
__device__ unsigned long long g_cellpack[NMAPS * NCELLS];
__device__ unsigned long long g_blockmin[NMAPS * BLOCKS_PER_MAP];
__device__ int g_ctr[NMAPS];         // self-resetting -> graph-replay safe

__device__ __forceinline__ void cp16(uint32_t smem_dst, const float* gmem_src) {
    asm volatile("cp.async.cg.shared.global [%0], [%1], 16;"
                 :: "r"(smem_dst), "l"(gmem_src));
}

// ---------------------------------------------------------------------------
// Fused kernel. Block = 256 threads = one grid-row of one map:
// 64 image rows x 1024 cols (16 cells). Thread t owns columns 4t..4t+3 for
// every row. cp.async 3-stage pipeline decouples HBM fetch from the
// argmax/argmin update chains. Last block per map runs selection.
// ---------------------------------------------------------------------------
__global__ __launch_bounds__(256) void k_fused(const float* __restrict__ sims,
                                               const int* __restrict__ osz,
                                               float* __restrict__ out,
                                               int write_nums, int nums_off) {
    __shared__ float4 sbuf[NSTAGES][RPS * 256];   // 48 KB staging

    const int b    = blockIdx.x;           // 0..511
    const int m    = b >> 4;               // map id
    const int gy   = b & 15;               // grid row within map
    const int tid  = threadIdx.x;
    const int warp = tid >> 5;
    const int lane = tid & 31;
    const int rowbase = gy << 6;           // first image row of this block

    const float* __restrict__ base = sims + (size_t)m * (H_DIM * W_DIM);
    const uint32_t sbase = (uint32_t)__cvta_generic_to_shared(&sbuf[0][0]);

    // ---- prologue: issue stages 0, 1 ----
    #pragma unroll
    for (int st = 0; st < NSTAGES - 1; ++st) {
        const float* src = base + ((unsigned)(rowbase + st * RPS) << 10) + ((unsigned)tid << 2);
        const uint32_t dst = sbase + ((unsigned)((st % NSTAGES) * RPS * 256 + tid) << 4);
        #pragma unroll
        for (int r = 0; r < RPS; ++r)
            cp16(dst + (unsigned)(r * 256 * 16), src + (r << 10));
        asm volatile("cp.async.commit_group;");
    }

    float    minv = __int_as_float(0x7f800000);      // +inf
    float    maxv = -minv;
    unsigned maxi = 0u, mini = 0u;
    const unsigned colbase = (unsigned)tid << 2;

    #pragma unroll
    for (int s = 0; s < NSTAGES_TOT; ++s) {
        if (s >= NSTAGES_TOT - (NSTAGES - 1))
            asm volatile("cp.async.wait_group 0;");
        else
            asm volatile("cp.async.wait_group %0;" :: "n"(NSTAGES - 2));
        __syncthreads();   // stage s visible to all; stage s-1 fully consumed

        // issue stage s + NSTAGES-1 (overwrites buffer of stage s-1: safe)
        if (s + NSTAGES - 1 < NSTAGES_TOT) {
            const int st = s + NSTAGES - 1;
            const float* src = base + ((unsigned)(rowbase + st * RPS) << 10) + colbase;
            const uint32_t dst = sbase + ((unsigned)((st % NSTAGES) * RPS * 256 + tid) << 4);
            #pragma unroll
            for (int r = 0; r < RPS; ++r)
                cp16(dst + (unsigned)(r * 256 * 16), src + (r << 10));
            asm volatile("cp.async.commit_group;");
        }

        // process stage s: rows ascend, strict cmp keeps earliest index
        const int buf = s % NSTAGES;
        #pragma unroll
        for (int r = 0; r < RPS; ++r) {
            const float4 v = sbuf[buf][r * 256 + tid];
            const unsigned idx = ((unsigned)(rowbase + s * RPS + r) << 10) + colbase;
            if (v.x > maxv) { maxv = v.x; maxi = idx;     }
            if (v.y > maxv) { maxv = v.y; maxi = idx + 1; }
            if (v.z > maxv) { maxv = v.z; maxi = idx + 2; }
            if (v.w > maxv) { maxv = v.w; maxi = idx + 3; }
            if (v.x < minv) { minv = v.x; mini = idx;     }
            if (v.y < minv) { minv = v.y; mini = idx + 1; }
            if (v.z < minv) { minv = v.z; mini = idx + 2; }
            if (v.w < minv) { minv = v.w; mini = idx + 3; }
        }
    }

    // ---- cell max: lexicographic reduce within each 16-lane group ----
    // (offsets 8,4,2,1: every source feeding lane 0 / lane 16 stays in-group)
    #pragma unroll
    for (int o = 8; o > 0; o >>= 1) {
        float    ov = __shfl_down_sync(0xffffffffu, maxv, o);
        unsigned oi = __shfl_down_sync(0xffffffffu, maxi, o);
        if (ov > maxv || (ov == maxv && oi < maxi)) { maxv = ov; maxi = oi; }
    }
    if ((lane & 15) == 0) {
        const int cid = (gy << 4) + (tid >> 4);          // cell id 0..255
        g_cellpack[m * NCELLS + cid] =
            ((unsigned long long)__float_as_uint(maxv) << 32) | (unsigned long long)maxi;
    }

    // ---- map min: full warp reduce, then block reduce ----
    #pragma unroll
    for (int o = 16; o > 0; o >>= 1) {
        float    nv = __shfl_down_sync(0xffffffffu, minv, o);
        unsigned ni = __shfl_down_sync(0xffffffffu, mini, o);
        if (nv < minv || (nv == minv && ni < mini)) { minv = nv; mini = ni; }
    }

    __shared__ unsigned long long sminkey[8];
    if (lane == 0) {
        // orderable transform (values are non-negative floats): bits ^ 0x80000000
        sminkey[warp] =
            ((unsigned long long)(__float_as_uint(minv) ^ 0x80000000u) << 32) |
            (unsigned long long)mini;
    }
    __syncthreads();

    __shared__ int s_last;
    if (tid == 0) {
        unsigned long long k = sminkey[0];
        #pragma unroll
        for (int j = 1; j < 8; ++j) k = min(k, sminkey[j]);
        g_blockmin[m * BLOCKS_PER_MAP + gy] = k;
        __threadfence();                          // publish cellpack + blockmin
        const int c = atomicAdd(&g_ctr[m], 1);
        s_last = (c == BLOCKS_PER_MAP - 1);
        if (s_last) g_ctr[m] = 0;                 // self-reset for graph replays
    }
    __syncthreads();
    if (!s_last) return;

    // ======================= selection phase (last block) ==================
    __shared__ float    sval[NCELLS];
    __shared__ unsigned sidx[NCELLS];
    __shared__ unsigned long long s_mink;

    const unsigned long long p = g_cellpack[m * NCELLS + tid];
    const float    v   = __uint_as_float((unsigned)(p >> 32));
    const unsigned idx = (unsigned)p;
    sval[tid] = v;
    sidx[tid] = idx;

    if (tid < 32) {                               // reduce the 16 block mins
        unsigned long long k = (tid < BLOCKS_PER_MAP)
            ? g_blockmin[m * BLOCKS_PER_MAP + tid] : ~0ULL;
        #pragma unroll
        for (int o = 8; o > 0; o >>= 1)
            k = min(k, __shfl_down_sync(0xffffffffu, k, o));
        if (tid == 0) s_mink = k;
    }

    float* __restrict__ orow = out + (size_t)m * (MAX_PTS * 4);
    if (tid < MAX_PTS) {
        reinterpret_cast<float4*>(orow)[tid] = make_float4(0.f, 0.f, 0.f, 0.f);
    }

    const bool valid   = (v > THRESH);
    const int  count   = __syncthreads_count(valid);   // barrier: sval/zero done
    const int  n_valid = count < NUM_FG ? count : NUM_FG;
    const bool any_fg  = (count > 0);

    const int   t  = m / C_DIM;
    const float sx = (float)osz[t * 2 + 1] / (float)W_DIM;
    const float sy = (float)osz[t * 2 + 0] / (float)H_DIM;

    // rank = #cells strictly better: (score desc, cell-id asc) == stable argsort
    const float NEGINF = -__int_as_float(0x7f800000);
    const float effv = valid ? v : NEGINF;
    int rank = 0;
    #pragma unroll 8
    for (int j = 0; j < NCELLS; ++j) {
        const float jv = sval[j];
        const float ej = (jv > THRESH) ? jv : NEGINF;
        rank += (int)((ej > effv) || (ej == effv && j < tid));
    }

    if (any_fg) {
        if (valid && rank < NUM_FG) {
            const float px = (float)(idx & (W_DIM - 1));
            const float py = (float)(idx >> 10);
            reinterpret_cast<float4*>(orow)[rank] =
                make_float4(px * sx, py * sy, v, 1.0f);
        }
    } else if (tid == 0) {
        // fallback: global argmax (value desc, idx asc) over cell maxima
        float    bv = sval[0];
        unsigned bi = sidx[0];
        for (int j = 1; j < NCELLS; ++j) {
            if (sval[j] > bv || (sval[j] == bv && sidx[j] < bi)) { bv = sval[j]; bi = sidx[j]; }
        }
        const float px = (float)(bi & (W_DIM - 1));
        const float py = (float)(bi >> 10);
        reinterpret_cast<float4*>(orow)[0] = make_float4(px * sx, py * sy, bv, 1.0f);
    }

    const int fg_count = any_fg ? n_valid : 1;
    if (tid == 0) {
        const unsigned long long k = s_mink;
        const float    bvv = __uint_as_float(((unsigned)(k >> 32)) ^ 0x80000000u);
        const unsigned bii = (unsigned)k;
        const float px = (float)(bii & (W_DIM - 1));
        const float py = (float)(bii >> 10);
        reinterpret_cast<float4*>(orow)[fg_count] =
            make_float4(px * sx, py * sy, bvv, 0.0f);
        if (write_nums)
            out[nums_off + m] = (float)(fg_count + NUM_BG);
    }
}

extern "C" void kernel_launch(void* const* d_in, const int* in_sizes, int n_in,
                              void* d_out, int out_size) {
    const float* sims = (const float*)d_in[0];
    // d_in[1] = category_ids (unused by the reference computation)
    const int* osz = (const int*)d_in[2];
    float* out = (float*)d_out;

    const int pts_elems = NMAPS * MAX_PTS * 4;                 // 5376
    const int write_nums = (out_size >= pts_elems + NMAPS) ? 1 : 0;

    k_fused<<<NMAPS * BLOCKS_PER_MAP, 256>>>(sims, osz, out, write_nums, pts_elems);
}

// round 8
// speedup vs baseline: 1.0203x; 1.0203x over previous
#include <cuda_runtime.h>
#include <cstdint>

// Problem constants
#define T_DIM 8
#define C_DIM 4
#define NMAPS (T_DIM * C_DIM)        // 32
#define H_DIM 1024
#define W_DIM 1024
#define NUM_GRID 16
#define NCELLS (NUM_GRID * NUM_GRID) // 256
#define THRESH 0.65f
#define NUM_FG 40
#define NUM_BG 1
#define MAX_PTS 42
#define BLOCKS_PER_MAP 32            // 8 warps/block, 1 cell per warp

// Scratch (__device__ globals; no allocations allowed)
__device__ unsigned long long g_cellpack[NMAPS * NCELLS];
__device__ unsigned long long g_blockmin[NMAPS * BLOCKS_PER_MAP];
__device__ int g_ctr[NMAPS];         // self-resetting -> graph-replay safe

typedef unsigned long long u64;

__device__ __forceinline__ u64 kmax2(u64 a, u64 b) { return a > b ? a : b; }
__device__ __forceinline__ u64 kmin2(u64 a, u64 b) { return a < b ? a : b; }

// 64-bit tournament keys. Values are non-negative fp32 -> raw bits are
// order-monotone. max key low word = ~idx  => max(key) = (max val, MIN idx).
// min key low word =  idx  => min(key) = (min val, MIN idx). Bit-exact.
__device__ __forceinline__ u64 MKX(float v, unsigned id) {
    return ((u64)__float_as_uint(v) << 32) | (unsigned)(~id);
}
__device__ __forceinline__ u64 MKN(float v, unsigned id) {
    return ((u64)__float_as_uint(v) << 32) | id;
}

// ---------------------------------------------------------------------------
// Fused kernel: per-cell max/argmax + per-map min via tournament keys, then
// the LAST block of each map performs selection + output assembly.
// grid = NMAPS * 32 blocks (8 warps = 8 cells each), block = 256 threads.
// ---------------------------------------------------------------------------
__global__ __launch_bounds__(256) void k_fused(const float* __restrict__ sims,
                                               const int* __restrict__ osz,
                                               float* __restrict__ out,
                                               int write_nums, int nums_off) {
    const int b    = blockIdx.x;          // 0..1023
    const int m    = b >> 5;              // map id
    const int binm = b & 31;              // block within map
    const int warp = threadIdx.x >> 5;
    const int lane = threadIdx.x & 31;
    const int cid  = (binm << 3) + warp;  // 0..255
    const int cy   = cid >> 4;
    const int cx   = cid & 15;

    const float* __restrict__ base = sims + (size_t)m * (H_DIM * W_DIM);
    const int rowsel = lane >> 4;                     // 0/1: which of 2 rows
    const int col    = (cx << 6) + ((lane & 15) << 2);
    const unsigned idx0 = (((unsigned)((cy << 6) + rowsel)) << 10) + (unsigned)col;

    u64 kmax = 0ull;                  // val 0 impossible to beat any real key? val>=0 -> min real key >= 0; start at 0 with ~idx=... safe: any real key has low word != matters only if valbits==0; uniform(0,1) >0. Use 0.
    u64 kmin = ~0ull;

    // 32 float4 per lane: 8 iterations x 4 front-batched LDG.128 (streaming)
    #pragma unroll
    for (int i = 0; i < 8; ++i) {
        const unsigned ib = idx0 + ((unsigned)i << 13);     // i*8 rows * 1024
        const float4 v0 = __ldcs(reinterpret_cast<const float4*>(base + ib));
        const float4 v1 = __ldcs(reinterpret_cast<const float4*>(base + ib + (2u << 10)));
        const float4 v2 = __ldcs(reinterpret_cast<const float4*>(base + ib + (4u << 10)));
        const float4 v3 = __ldcs(reinterpret_cast<const float4*>(base + ib + (6u << 10)));

        // per-float4 balanced trees (independent ops), one running update each
        #define KEYS(v, off) do {                                            \
            const unsigned _i = ib + (unsigned)(off);                        \
            u64 a = MKX((v).x, _i),     bb = MKX((v).y, _i + 1);             \
            u64 c = MKX((v).z, _i + 2), d  = MKX((v).w, _i + 3);             \
            kmax = kmax2(kmax, kmax2(kmax2(a, bb), kmax2(c, d)));            \
            a = MKN((v).x, _i);     bb = MKN((v).y, _i + 1);                 \
            c = MKN((v).z, _i + 2); d  = MKN((v).w, _i + 3);                 \
            kmin = kmin2(kmin, kmin2(kmin2(a, bb), kmin2(c, d)));            \
        } while (0)
        KEYS(v0, 0);
        KEYS(v1, 2u << 10);
        KEYS(v2, 4u << 10);
        KEYS(v3, 6u << 10);
        #undef KEYS
    }

    // warp reduction on keys
    #pragma unroll
    for (int o = 16; o > 0; o >>= 1) {
        kmax = kmax2(kmax, __shfl_down_sync(0xffffffffu, kmax, o));
        kmin = kmin2(kmin, __shfl_down_sync(0xffffffffu, kmin, o));
    }

    __shared__ u64 sminkey[8];
    if (lane == 0) {
        // cellpack format: (val bits << 32) | argmax index
        g_cellpack[m * NCELLS + cid] =
            (kmax & 0xFFFFFFFF00000000ull) | (unsigned)(~(unsigned)kmax);
        sminkey[warp] = kmin;         // already orderable: (val bits<<32)|idx
    }
    __syncthreads();

    __shared__ int s_last;
    if (threadIdx.x == 0) {
        u64 k = sminkey[0];
        #pragma unroll
        for (int j = 1; j < 8; ++j) k = kmin2(k, sminkey[j]);
        g_blockmin[m * BLOCKS_PER_MAP + binm] = k;
        __threadfence();                          // publish cellpack + blockmin
        const int c = atomicAdd(&g_ctr[m], 1);
        s_last = (c == BLOCKS_PER_MAP - 1);
        if (s_last) g_ctr[m] = 0;                 // self-reset for graph replays
    }
    __syncthreads();
    if (!s_last) return;

    // ======================= selection phase (last block) ==================
    const int tid = threadIdx.x;                  // == cell id

    __shared__ float    sval[NCELLS];
    __shared__ unsigned sidx[NCELLS];
    __shared__ u64 s_mink;

    const u64 p = g_cellpack[m * NCELLS + tid];
    const float    v   = __uint_as_float((unsigned)(p >> 32));
    const unsigned idx = (unsigned)p;
    sval[tid] = v;
    sidx[tid] = idx;

    if (tid < 32) {                               // reduce the 32 block mins
        u64 k = g_blockmin[m * BLOCKS_PER_MAP + tid];
        #pragma unroll
        for (int o = 16; o > 0; o >>= 1)
            k = kmin2(k, __shfl_down_sync(0xffffffffu, k, o));
        if (tid == 0) s_mink = k;
    }

    float* __restrict__ orow = out + (size_t)m * (MAX_PTS * 4);
    if (tid < MAX_PTS) {
        reinterpret_cast<float4*>(orow)[tid] = make_float4(0.f, 0.f, 0.f, 0.f);
    }

    const bool valid   = (v > THRESH);
    const int  count   = __syncthreads_count(valid);   // barrier: sval/zero done
    const int  n_valid = count < NUM_FG ? count : NUM_FG;
    const bool any_fg  = (count > 0);

    const int   t  = m / C_DIM;
    const float sx = (float)osz[t * 2 + 1] / (float)W_DIM;
    const float sy = (float)osz[t * 2 + 0] / (float)H_DIM;

    // rank = #cells strictly better: (score desc, cell-id asc) == stable argsort
    const float NEGINF = -__int_as_float(0x7f800000);
    const float effv = valid ? v : NEGINF;
    int rank = 0;
    #pragma unroll 8
    for (int j = 0; j < NCELLS; ++j) {
        const float jv = sval[j];
        const float ej = (jv > THRESH) ? jv : NEGINF;
        rank += (int)((ej > effv) || (ej == effv && j < tid));
    }

    if (any_fg) {
        if (valid && rank < NUM_FG) {
            const float px = (float)(idx & (W_DIM - 1));
            const float py = (float)(idx >> 10);
            reinterpret_cast<float4*>(orow)[rank] =
                make_float4(px * sx, py * sy, v, 1.0f);
        }
    } else if (tid == 0) {
        // fallback: global argmax (value desc, idx asc) over cell maxima
        float    bv = sval[0];
        unsigned bi = sidx[0];
        for (int j = 1; j < NCELLS; ++j) {
            if (sval[j] > bv || (sval[j] == bv && sidx[j] < bi)) { bv = sval[j]; bi = sidx[j]; }
        }
        const float px = (float)(bi & (W_DIM - 1));
        const float py = (float)(bi >> 10);
        reinterpret_cast<float4*>(orow)[0] = make_float4(px * sx, py * sy, bv, 1.0f);
    }

    const int fg_count = any_fg ? n_valid : 1;
    if (tid == 0) {
        const u64 k = s_mink;
        const float    bvv = __uint_as_float((unsigned)(k >> 32));
        const unsigned bii = (unsigned)k;
        const float px = (float)(bii & (W_DIM - 1));
        const float py = (float)(bii >> 10);
        reinterpret_cast<float4*>(orow)[fg_count] =
            make_float4(px * sx, py * sy, bvv, 0.0f);
        if (write_nums)
            out[nums_off + m] = (float)(fg_count + NUM_BG);
    }
}

extern "C" void kernel_launch(void* const* d_in, const int* in_sizes, int n_in,
                              void* d_out, int out_size) {
    const float* sims = (const float*)d_in[0];
    // d_in[1] = category_ids (unused by the reference computation)
    const int* osz = (const int*)d_in[2];
    float* out = (float*)d_out;

    const int pts_elems = NMAPS * MAX_PTS * 4;                 // 5376
    const int write_nums = (out_size >= pts_elems + NMAPS) ? 1 : 0;

    k_fused<<<NMAPS * BLOCKS_PER_MAP, 256>>>(sims, osz, out, write_nums, pts_elems);
}

// round 10
// speedup vs baseline: 1.1136x; 1.0914x over previous
#include <cuda_runtime.h>
#include <cstdint>

// Problem constants
#define T_DIM 8
#define C_DIM 4
#define NMAPS (T_DIM * C_DIM)        // 32
#define H_DIM 1024
#define W_DIM 1024
#define NUM_GRID 16
#define NCELLS (NUM_GRID * NUM_GRID) // 256
#define THRESH 0.65f
#define NUM_FG 40
#define NUM_BG 1
#define MAX_PTS 42
#define BLOCKS_PER_MAP 32            // 8 warps/block, 1 cell per warp

// Scratch (__device__ globals; no allocations allowed)
__device__ unsigned long long g_cellpack[NMAPS * NCELLS];
__device__ unsigned long long g_blockmin[NMAPS * BLOCKS_PER_MAP];
__device__ int g_ctr[NMAPS];         // self-resetting -> graph-replay safe

// ---------------------------------------------------------------------------
// Fused kernel: per-cell max/argmax + per-map min, then the LAST block of
// each map performs selection + output assembly.
// grid = NMAPS*32 blocks (8 warps = 8 cells each), block = 256 threads.
// launch_bounds(256,8): regs<=32 -> 8 CTAs/SM -> 1184 CTA capacity -> 1 wave.
// ---------------------------------------------------------------------------
__global__ __launch_bounds__(256, 8) void k_fused(const float* __restrict__ sims,
                                                  const int* __restrict__ osz,
                                                  float* __restrict__ out,
                                                  int write_nums, int nums_off) {
    const int b    = blockIdx.x;          // 0..1023
    const int m    = b >> 5;              // map id
    const int binm = b & 31;              // block within map
    const int warp = threadIdx.x >> 5;
    const int lane = threadIdx.x & 31;
    const int cid  = (binm << 3) + warp;  // 0..255
    const int cy   = cid >> 4;
    const int cx   = cid & 15;

    const float* __restrict__ base = sims + (size_t)m * (H_DIM * W_DIM);
    const int rowsel = lane >> 4;                     // 0/1: which of 2 rows
    const int col    = (cx << 6) + ((lane & 15) << 2);
    const unsigned idx0 = (((unsigned)((cy << 6) + rowsel)) << 10) + (unsigned)col;

    float    minv = __int_as_float(0x7f800000);       // +inf
    float    maxv = -minv;
    unsigned maxi = 0u, mini = 0u;

    // 32 float4 per lane; per float4: 4-elem tournament tree (3 cmp) + one
    // running update per direction. Strict compares keep EARLIEST index at
    // every level (indices ascend within the float4 / across iterations).
    #pragma unroll
    for (int i = 0; i < 32; ++i) {
        const unsigned idx = idx0 + ((unsigned)i << 11);      // +2 rows/iter
        const float4 v = __ldcg(reinterpret_cast<const float4*>(base + idx));

        // --- max tree ---
        float    m01 = fmaxf(v.x, v.y);
        unsigned i01 = (v.y > v.x) ? idx + 1 : idx;
        float    m23 = fmaxf(v.z, v.w);
        unsigned i23 = (v.w > v.z) ? idx + 3 : idx + 2;
        float    mq  = fmaxf(m01, m23);
        unsigned iq  = (m23 > m01) ? i23 : i01;
        if (mq > maxv) { maxv = mq; maxi = iq; }

        // --- min tree ---
        float    n01 = fminf(v.x, v.y);
        unsigned j01 = (v.y < v.x) ? idx + 1 : idx;
        float    n23 = fminf(v.z, v.w);
        unsigned j23 = (v.w < v.z) ? idx + 3 : idx + 2;
        float    nq  = fminf(n01, n23);
        unsigned jq  = (n23 < n01) ? j23 : j01;
        if (nq < minv) { minv = nq; mini = jq; }
    }

    // warp lexicographic reduce: (max val, min idx) / (min val, min idx)
    #pragma unroll
    for (int o = 16; o > 0; o >>= 1) {
        float    ov = __shfl_down_sync(0xffffffffu, maxv, o);
        unsigned oi = __shfl_down_sync(0xffffffffu, maxi, o);
        if (ov > maxv || (ov == maxv && oi < maxi)) { maxv = ov; maxi = oi; }
        float    nv = __shfl_down_sync(0xffffffffu, minv, o);
        unsigned ni = __shfl_down_sync(0xffffffffu, mini, o);
        if (nv < minv || (nv == minv && ni < mini)) { minv = nv; mini = ni; }
    }

    __shared__ unsigned long long sminkey[8];
    if (lane == 0) {
        g_cellpack[m * NCELLS + cid] =
            ((unsigned long long)__float_as_uint(maxv) << 32) | (unsigned long long)maxi;
        // orderable transform (values are non-negative floats): bits ^ 0x80000000
        sminkey[warp] =
            ((unsigned long long)(__float_as_uint(minv) ^ 0x80000000u) << 32) |
            (unsigned long long)mini;
    }
    __syncthreads();

    __shared__ int s_last;
    if (threadIdx.x == 0) {
        unsigned long long k = sminkey[0];
        #pragma unroll
        for (int j = 1; j < 8; ++j) k = min(k, sminkey[j]);
        g_blockmin[m * BLOCKS_PER_MAP + binm] = k;
        __threadfence();                          // publish cellpack + blockmin
        const int c = atomicAdd(&g_ctr[m], 1);
        s_last = (c == BLOCKS_PER_MAP - 1);
        if (s_last) g_ctr[m] = 0;                 // self-reset for graph replays
    }
    __syncthreads();
    if (!s_last) return;

    // ======================= selection phase (last block) ==================
    const int tid = threadIdx.x;                  // == cell id

    __shared__ float    sval[NCELLS];
    __shared__ unsigned sidx[NCELLS];
    __shared__ unsigned long long s_mink;

    const unsigned long long p = g_cellpack[m * NCELLS + tid];
    const float    v   = __uint_as_float((unsigned)(p >> 32));
    const unsigned idx = (unsigned)p;
    sval[tid] = v;
    sidx[tid] = idx;

    if (tid < 32) {                               // reduce the 32 block mins
        unsigned long long k = g_blockmin[m * BLOCKS_PER_MAP + tid];
        #pragma unroll
        for (int o = 16; o > 0; o >>= 1)
            k = min(k, __shfl_down_sync(0xffffffffu, k, o));
        if (tid == 0) s_mink = k;
    }

    float* __restrict__ orow = out + (size_t)m * (MAX_PTS * 4);
    if (tid < MAX_PTS) {
        reinterpret_cast<float4*>(orow)[tid] = make_float4(0.f, 0.f, 0.f, 0.f);
    }

    const bool valid   = (v > THRESH);
    const int  count   = __syncthreads_count(valid);   // barrier: sval/zero done
    const int  n_valid = count < NUM_FG ? count : NUM_FG;
    const bool any_fg  = (count > 0);

    const int   t  = m / C_DIM;
    const float sx = (float)osz[t * 2 + 1] / (float)W_DIM;
    const float sy = (float)osz[t * 2 + 0] / (float)H_DIM;

    // rank = #cells strictly better: (score desc, cell-id asc) == stable argsort
    const float NEGINF = -__int_as_float(0x7f800000);
    const float effv = valid ? v : NEGINF;
    int rank = 0;
    #pragma unroll 8
    for (int j = 0; j < NCELLS; ++j) {
        const float jv = sval[j];
        const float ej = (jv > THRESH) ? jv : NEGINF;
        rank += (int)((ej > effv) || (ej == effv && j < tid));
    }

    if (any_fg) {
        if (valid && rank < NUM_FG) {
            const float px = (float)(idx & (W_DIM - 1));
            const float py = (float)(idx >> 10);
            reinterpret_cast<float4*>(orow)[rank] =
                make_float4(px * sx, py * sy, v, 1.0f);
        }
    } else if (tid == 0) {
        // fallback: global argmax (value desc, idx asc) over cell maxima
        float    bv = sval[0];
        unsigned bi = sidx[0];
        for (int j = 1; j < NCELLS; ++j) {
            if (sval[j] > bv || (sval[j] == bv && sidx[j] < bi)) { bv = sval[j]; bi = sidx[j]; }
        }
        const float px = (float)(bi & (W_DIM - 1));
        const float py = (float)(bi >> 10);
        reinterpret_cast<float4*>(orow)[0] = make_float4(px * sx, py * sy, bv, 1.0f);
    }

    const int fg_count = any_fg ? n_valid : 1;
    if (tid == 0) {
        const unsigned long long k = s_mink;
        const float    bvv = __uint_as_float(((unsigned)(k >> 32)) ^ 0x80000000u);
        const unsigned bii = (unsigned)k;
        const float px = (float)(bii & (W_DIM - 1));
        const float py = (float)(bii >> 10);
        reinterpret_cast<float4*>(orow)[fg_count] =
            make_float4(px * sx, py * sy, bvv, 0.0f);
        if (write_nums)
            out[nums_off + m] = (float)(fg_count + NUM_BG);
    }
}

extern "C" void kernel_launch(void* const* d_in, const int* in_sizes, int n_in,
                              void* d_out, int out_size) {
    const float* sims = (const float*)d_in[0];
    // d_in[1] = category_ids (unused by the reference computation)
    const int* osz = (const int*)d_in[2];
    float* out = (float*)d_out;

    const int pts_elems = NMAPS * MAX_PTS * 4;                 // 5376
    const int write_nums = (out_size >= pts_elems + NMAPS) ? 1 : 0;

    k_fused<<<NMAPS * BLOCKS_PER_MAP, 256>>>(sims, osz, out, write_nums, pts_elems);
}